// round 1
// baseline (speedup 1.0000x reference)
#include <cuda_runtime.h>
#include <cuda_bf16.h>
#include <cstdint>

// RankPooling via Woodbury identity:
//   w = X (alpha*I + X^T X)^{-1} y,  alpha = 1/(2C) = 50000, y = [1..T]
// Phase 1: S = X^T X via bf16 mma.sync (fp32 accum), per-CTA (one batch each)
// Phase 2: Jacobi/Neumann fixed point v <- (y - S v)/alpha  (16 iters, smem)
// Phase 3: w = X v in fp32 (re-read of X, mostly L2-resident)

#define D_SZ 768
#define T_SZ 128
#define DT   32            // d-rows per smem tile
#define NT   (D_SZ / DT)   // 24 tiles
#define TP   136           // bf16 tile pitch (elements) -> 272B rows, conflict-free ldmatrix
#define SP   129           // S fp32 pitch (odd -> conflict-free row reads)
#define ALPHA_INV 2.0e-5f
#define NITER 16

__device__ __forceinline__ uint32_t sptr(const void* p) {
    return (uint32_t)__cvta_generic_to_shared(p);
}
__device__ __forceinline__ uint32_t pack_bf16(float a, float b) {
    __nv_bfloat162 h = __floats2bfloat162_rn(a, b);
    return *reinterpret_cast<uint32_t*>(&h);
}

#define LDSM_T4(R, addr) \
    asm volatile("ldmatrix.sync.aligned.m8n8.x4.trans.shared.b16 {%0,%1,%2,%3}, [%4];" \
        : "=r"(R[0]), "=r"(R[1]), "=r"(R[2]), "=r"(R[3]) : "r"(addr))

#define MMA16816(d, a, b0, b1) \
    asm volatile("mma.sync.aligned.m16n8k16.row.col.f32.bf16.bf16.f32 " \
        "{%0,%1,%2,%3},{%4,%5,%6,%7},{%8,%9},{%0,%1,%2,%3};" \
        : "+f"(d[0]), "+f"(d[1]), "+f"(d[2]), "+f"(d[3]) \
        : "r"(a[0]), "r"(a[1]), "r"(a[2]), "r"(a[3]), "r"(b0), "r"(b1))

extern __shared__ float smem_f[];

__global__ void __launch_bounds__(256, 2)
rankpool_kernel(const float* __restrict__ X, float* __restrict__ out)
{
    const int b    = blockIdx.x;
    const int tid  = threadIdx.x;
    const int wid  = tid >> 5;
    const int lane = tid & 31;

    const float*  Xb  = X + (size_t)b * (D_SZ * T_SZ);
    const float4* Xb4 = reinterpret_cast<const float4*>(Xb);

    // ---------------- Phase 1: S = X^T X ----------------
    char* tile = reinterpret_cast<char*>(smem_f);
    const uint32_t sbase = sptr(smem_f);

    // warp layout over the 128x128 S output: 4 (m) x 2 (n)
    const int m_base = (wid >> 1) << 5;   // 0,32,64,96
    const int n_base = (wid & 1) << 6;    // 0,64

    // ldmatrix.trans address patterns (tile is M[k_local][t], k-major rows)
    const int a_row = (lane & 7) | ((lane >> 4) << 3);
    const int a_col = ((lane >> 3) & 1) << 3;
    uint32_t a_addr[2], b_addr[4];
    #pragma unroll
    for (int mt = 0; mt < 2; mt++)
        a_addr[mt] = sbase + a_row * (TP * 2) + (m_base + 16 * mt + a_col) * 2;
    #pragma unroll
    for (int bt = 0; bt < 4; bt++)
        b_addr[bt] = sbase + (lane & 15) * (TP * 2)
                   + (n_base + 16 * bt + ((lane >> 4) << 3)) * 2;

    float acc[2][8][4];
    #pragma unroll
    for (int mi = 0; mi < 2; mi++)
        #pragma unroll
        for (int ni = 0; ni < 8; ni++)
            #pragma unroll
            for (int r = 0; r < 4; r++) acc[mi][ni][r] = 0.f;

    // register-staged global load (software pipeline)
    const int srow = tid >> 5;  // 0..7
    const int c4   = tid & 31;  // float4 column
    float4 st[4];
    #pragma unroll
    for (int j = 0; j < 4; j++)
        st[j] = Xb4[(srow + 8 * j) * 32 + c4];

    for (int t = 0; t < NT; t++) {
        // store staged tile -> smem as bf16 (transpose-free; tile stays d-major)
        #pragma unroll
        for (int j = 0; j < 4; j++) {
            uint32_t u0 = pack_bf16(st[j].x, st[j].y);
            uint32_t u1 = pack_bf16(st[j].z, st[j].w);
            *reinterpret_cast<uint2*>(tile + (srow + 8 * j) * (TP * 2) + c4 * 8)
                = make_uint2(u0, u1);
        }
        __syncthreads();
        if (t + 1 < NT) {
            #pragma unroll
            for (int j = 0; j < 4; j++)
                st[j] = Xb4[(DT * (t + 1) + srow + 8 * j) * 32 + c4];
        }
        #pragma unroll
        for (int ks = 0; ks < 2; ks++) {
            const uint32_t koff = (uint32_t)ks * 16 * (TP * 2);
            uint32_t af[2][4], bf[4][4];
            LDSM_T4(af[0], a_addr[0] + koff);
            LDSM_T4(af[1], a_addr[1] + koff);
            #pragma unroll
            for (int bt = 0; bt < 4; bt++) LDSM_T4(bf[bt], b_addr[bt] + koff);
            #pragma unroll
            for (int mi = 0; mi < 2; mi++)
                #pragma unroll
                for (int ni = 0; ni < 8; ni++)
                    MMA16816(acc[mi][ni], af[mi],
                             bf[ni >> 1][(ni & 1) * 2], bf[ni >> 1][(ni & 1) * 2 + 1]);
        }
        __syncthreads();
    }

    // write accumulators -> S in smem (fp32, pitch SP)
    float* Ssm = smem_f;
    {
        const int gid = lane >> 2, t4 = lane & 3;
        #pragma unroll
        for (int mi = 0; mi < 2; mi++)
            #pragma unroll
            for (int ni = 0; ni < 8; ni++) {
                int r0 = m_base + 16 * mi + gid;
                int c0 = n_base + 8 * ni + 2 * t4;
                Ssm[r0 * SP + c0]           = acc[mi][ni][0];
                Ssm[r0 * SP + c0 + 1]       = acc[mi][ni][1];
                Ssm[(r0 + 8) * SP + c0]     = acc[mi][ni][2];
                Ssm[(r0 + 8) * SP + c0 + 1] = acc[mi][ni][3];
            }
    }

    // ---------------- Phase 2: solve (alpha*I + S) v = y ----------------
    float* va = smem_f + 128 * SP;
    float* vb = va + 128;
    if (tid < 128) va[tid] = 0.f;
    __syncthreads();

    const float yv = (float)(tid + 1);
    #pragma unroll 1
    for (int it = 0; it < NITER; it++) {
        float* cur = (it & 1) ? vb : va;
        float* nxt = (it & 1) ? va : vb;
        if (tid < 128) {
            const float* Srow = Ssm + tid * SP;
            float sum = 0.f;
            #pragma unroll 8
            for (int j = 0; j < 128; j++) sum += Srow[j] * cur[j];
            nxt[tid] = (yv - sum) * ALPHA_INV;
        }
        __syncthreads();
    }
    // NITER even -> result lives in va

    // ---------------- Phase 3: w = X v (fp32) ----------------
    const float4* vf4 = reinterpret_cast<const float4*>(va);
    const float4  vv  = vf4[lane];
    float* outb = out + b * D_SZ;

    #pragma unroll 1
    for (int r0 = 0; r0 < 96; r0 += 4) {
        float4 xr[4];
        #pragma unroll
        for (int i = 0; i < 4; i++)
            xr[i] = Xb4[(wid + 8 * (r0 + i)) * 32 + lane];
        float s[4];
        #pragma unroll
        for (int i = 0; i < 4; i++) {
            float tv = xr[i].x * vv.x + xr[i].y * vv.y + xr[i].z * vv.z + xr[i].w * vv.w;
            tv += __shfl_xor_sync(0xffffffffu, tv, 16);
            tv += __shfl_xor_sync(0xffffffffu, tv, 8);
            tv += __shfl_xor_sync(0xffffffffu, tv, 4);
            tv += __shfl_xor_sync(0xffffffffu, tv, 2);
            tv += __shfl_xor_sync(0xffffffffu, tv, 1);
            s[i] = tv;
        }
        if (lane == 0) {
            #pragma unroll
            for (int i = 0; i < 4; i++) outb[wid + 8 * (r0 + i)] = s[i];
        }
    }
}

extern "C" void kernel_launch(void* const* d_in, const int* in_sizes, int n_in,
                              void* d_out, int out_size)
{
    const float* X   = (const float*)d_in[0];
    float*       out = (float*)d_out;

    const int smem_bytes = (128 * SP + 256) * 4;  // S + v ping-pong (~67.1 KB)
    cudaFuncSetAttribute(rankpool_kernel,
                         cudaFuncAttributeMaxDynamicSharedMemorySize, smem_bytes);
    rankpool_kernel<<<256, 256, smem_bytes>>>(X, out);
}

// round 3
// speedup vs baseline: 1.3899x; 1.3899x over previous
#include <cuda_runtime.h>
#include <cuda_bf16.h>
#include <cstdint>

// RankPooling via Woodbury identity:
//   w = X (alpha*I + X^T X)^{-1} y,  alpha = 1/(2C) = 50000, y = [1..T]
// Phase 1: S = X^T X via bf16 mma.sync (fp32 accum), double-buffered smem tiles
// Phase 2: Jacobi fixed point v <- (y - S v)/alpha, 6 iters, 256 threads,
//          swizzled pitch-128 S layout -> conflict-free float4 LDS
// Phase 3: w = X v in fp32 (second pass, mostly L2-resident), 8-row ILP

#define D_SZ 768
#define T_SZ 128
#define DT   32              // d-rows per smem tile
#define NT   (D_SZ / DT)     // 24 tiles
#define TP   136             // bf16 tile pitch (elems) -> 272B rows, conflict-free ldmatrix
#define TILE_BYTES (DT * TP * 2)   // 8704
#define ALPHA_INV 2.0e-5f
#define NITER 6              // even -> result ends in va

__device__ __forceinline__ uint32_t sptr(const void* p) {
    return (uint32_t)__cvta_generic_to_shared(p);
}
__device__ __forceinline__ uint32_t pack_bf16(float a, float b) {
    __nv_bfloat162 h = __floats2bfloat162_rn(a, b);
    return *reinterpret_cast<uint32_t*>(&h);
}

#define LDSM_T4(R, addr) \
    asm volatile("ldmatrix.sync.aligned.m8n8.x4.trans.shared.b16 {%0,%1,%2,%3}, [%4];" \
        : "=r"(R[0]), "=r"(R[1]), "=r"(R[2]), "=r"(R[3]) : "r"(addr))

#define MMA16816(d, a, b0, b1) \
    asm volatile("mma.sync.aligned.m16n8k16.row.col.f32.bf16.bf16.f32 " \
        "{%0,%1,%2,%3},{%4,%5,%6,%7},{%8,%9},{%0,%1,%2,%3};" \
        : "+f"(d[0]), "+f"(d[1]), "+f"(d[2]), "+f"(d[3]) \
        : "r"(a[0]), "r"(a[1]), "r"(a[2]), "r"(a[3]), "r"(b0), "r"(b1))

extern __shared__ float smem_f[];

// S element (r, j) lives at r*128 + ((j4 ^ (r&31))<<2) + (j&3)   [float index]
__device__ __forceinline__ int s_idx(int r, int j) {
    int j4 = j >> 2;
    return (r << 7) + (((j4 ^ (r & 31)) << 2) | (j & 3));
}

__global__ void __launch_bounds__(256, 2)
rankpool_kernel(const float* __restrict__ X, float* __restrict__ out)
{
    const int b    = blockIdx.x;
    const int tid  = threadIdx.x;
    const int wid  = tid >> 5;
    const int lane = tid & 31;

    const float*  Xb  = X + (size_t)b * (D_SZ * T_SZ);
    const float4* Xb4 = reinterpret_cast<const float4*>(Xb);

    // ---------------- Phase 1: S = X^T X (double-buffered) ----------------
    char* tile = reinterpret_cast<char*>(smem_f);
    const uint32_t sbase = sptr(smem_f);

    // warp layout over the 128x128 S output: 4 (m) x 2 (n)
    const int m_base = (wid >> 1) << 5;   // 0,32,64,96
    const int n_base = (wid & 1) << 6;    // 0,64

    // ldmatrix.trans address patterns (tile is M[k_local][t], k-major rows)
    const int a_row = (lane & 7) | ((lane >> 4) << 3);
    const int a_col = ((lane >> 3) & 1) << 3;
    uint32_t a_addr[2], b_addr[4];
    #pragma unroll
    for (int mt = 0; mt < 2; mt++)
        a_addr[mt] = sbase + a_row * (TP * 2) + (m_base + 16 * mt + a_col) * 2;
    #pragma unroll
    for (int bt = 0; bt < 4; bt++)
        b_addr[bt] = sbase + (lane & 15) * (TP * 2)
                   + (n_base + 16 * bt + ((lane >> 4) << 3)) * 2;

    float acc[2][8][4];
    #pragma unroll
    for (int mi = 0; mi < 2; mi++)
        #pragma unroll
        for (int ni = 0; ni < 8; ni++)
            #pragma unroll
            for (int r = 0; r < 4; r++) acc[mi][ni][r] = 0.f;

    // register-staged global load (software pipeline)
    const int srow = tid >> 5;  // 0..7
    const int c4   = tid & 31;  // float4 column
    float4 st[4];
    #pragma unroll
    for (int j = 0; j < 4; j++)
        st[j] = Xb4[(srow + 8 * j) * 32 + c4];

    #pragma unroll 1
    for (int t = 0; t < NT; t++) {
        const uint32_t boff = (uint32_t)(t & 1) * TILE_BYTES;
        // store staged tile -> smem bf16 (buffer t&1)
        #pragma unroll
        for (int j = 0; j < 4; j++) {
            uint32_t u0 = pack_bf16(st[j].x, st[j].y);
            uint32_t u1 = pack_bf16(st[j].z, st[j].w);
            *reinterpret_cast<uint2*>(tile + boff + (srow + 8 * j) * (TP * 2) + c4 * 8)
                = make_uint2(u0, u1);
        }
        __syncthreads();   // single barrier per tile (double buffer)
        if (t + 1 < NT) {
            #pragma unroll
            for (int j = 0; j < 4; j++)
                st[j] = Xb4[(DT * (t + 1) + srow + 8 * j) * 32 + c4];
        }
        #pragma unroll
        for (int ks = 0; ks < 2; ks++) {
            const uint32_t koff = boff + (uint32_t)ks * 16 * (TP * 2);
            uint32_t af[2][4], bf[4][4];
            LDSM_T4(af[0], a_addr[0] + koff);
            LDSM_T4(af[1], a_addr[1] + koff);
            #pragma unroll
            for (int bt = 0; bt < 4; bt++) LDSM_T4(bf[bt], b_addr[bt] + koff);
            #pragma unroll
            for (int mi = 0; mi < 2; mi++)
                #pragma unroll
                for (int ni = 0; ni < 8; ni++)
                    MMA16816(acc[mi][ni], af[mi],
                             bf[ni >> 1][(ni & 1) * 2], bf[ni >> 1][(ni & 1) * 2 + 1]);
        }
    }
    __syncthreads();   // all LDSM reads done before S overwrites tile smem

    // write accumulators -> S in smem (fp32, pitch 128, float4-swizzled)
    float* Ssm = smem_f;
    {
        const int gid = lane >> 2, t4 = lane & 3;
        #pragma unroll
        for (int mi = 0; mi < 2; mi++)
            #pragma unroll
            for (int ni = 0; ni < 8; ni++) {
                int r0 = m_base + 16 * mi + gid;
                int c0 = n_base + 8 * ni + 2 * t4;
                Ssm[s_idx(r0, c0)]         = acc[mi][ni][0];
                Ssm[s_idx(r0, c0 + 1)]     = acc[mi][ni][1];
                Ssm[s_idx(r0 + 8, c0)]     = acc[mi][ni][2];
                Ssm[s_idx(r0 + 8, c0 + 1)] = acc[mi][ni][3];
            }
    }

    // ---------------- Phase 2: solve (alpha*I + S) v = y ----------------
    float* va = smem_f + 128 * 128;       // 16B aligned
    float* vb = va + 128;
    float* pp = vb + 128;                 // partials [128]

    const int r2 = tid & 127;
    const int h2 = tid >> 7;
    if (h2 == 0) va[r2] = (float)(r2 + 1) * ALPHA_INV;   // v0 = y/alpha
    __syncthreads();

    const float4* S4 = reinterpret_cast<const float4*>(Ssm);
    const int rsw = r2 & 31;
    const float yv = (float)(r2 + 1);

    #pragma unroll 1
    for (int it = 0; it < NITER; it++) {
        const float* cur = (it & 1) ? vb : va;
        float* nxt       = (it & 1) ? va : vb;
        const float4* V4 = reinterpret_cast<const float4*>(cur);

        float4 s0 = make_float4(0.f, 0.f, 0.f, 0.f);
        float4 s1 = make_float4(0.f, 0.f, 0.f, 0.f);
        #pragma unroll
        for (int j4 = 16 * h2; j4 < 16 * h2 + 16; j4 += 2) {
            float4 a0 = S4[(r2 << 5) + (j4 ^ rsw)];
            float4 a1 = S4[(r2 << 5) + ((j4 + 1) ^ rsw)];
            float4 v0 = V4[j4];
            float4 v1 = V4[j4 + 1];
            s0.x = fmaf(a0.x, v0.x, s0.x); s0.y = fmaf(a0.y, v0.y, s0.y);
            s0.z = fmaf(a0.z, v0.z, s0.z); s0.w = fmaf(a0.w, v0.w, s0.w);
            s1.x = fmaf(a1.x, v1.x, s1.x); s1.y = fmaf(a1.y, v1.y, s1.y);
            s1.z = fmaf(a1.z, v1.z, s1.z); s1.w = fmaf(a1.w, v1.w, s1.w);
        }
        float part = (s0.x + s0.y) + (s0.z + s0.w) + (s1.x + s1.y) + (s1.z + s1.w);
        if (h2 == 1) pp[r2] = part;
        __syncthreads();
        if (h2 == 0) nxt[r2] = (yv - part - pp[r2]) * ALPHA_INV;
        __syncthreads();
    }
    // NITER even -> result in va

    // ---------------- Phase 3: w = X v (fp32), 8 rows per pass ----------------
    const float4* vf4 = reinterpret_cast<const float4*>(va);
    const float4  vv  = vf4[lane];
    float* outb = out + b * D_SZ;

    #pragma unroll 1
    for (int r0 = 0; r0 < 96; r0 += 8) {
        float4 xr[8];
        #pragma unroll
        for (int i = 0; i < 8; i++)
            xr[i] = Xb4[(wid + 8 * (r0 + i)) * 32 + lane];
        float s[8];
        #pragma unroll
        for (int i = 0; i < 8; i++) {
            float tv = fmaf(xr[i].x, vv.x, fmaf(xr[i].y, vv.y,
                       fmaf(xr[i].z, vv.z, xr[i].w * vv.w)));
            tv += __shfl_xor_sync(0xffffffffu, tv, 16);
            tv += __shfl_xor_sync(0xffffffffu, tv, 8);
            tv += __shfl_xor_sync(0xffffffffu, tv, 4);
            tv += __shfl_xor_sync(0xffffffffu, tv, 2);
            tv += __shfl_xor_sync(0xffffffffu, tv, 1);
            s[i] = tv;
        }
        if (lane == 0) {
            #pragma unroll
            for (int i = 0; i < 8; i++) outb[wid + 8 * (r0 + i)] = s[i];
        }
    }
}

extern "C" void kernel_launch(void* const* d_in, const int* in_sizes, int n_in,
                              void* d_out, int out_size)
{
    const float* X   = (const float*)d_in[0];
    float*       out = (float*)d_out;

    const int smem_bytes = (128 * 128 + 3 * 128) * 4;  // S (64KB) + va/vb/pp
    cudaFuncSetAttribute(rankpool_kernel,
                         cudaFuncAttributeMaxDynamicSharedMemorySize, smem_bytes);
    rankpool_kernel<<<256, 256, smem_bytes>>>(X, out);
}